// round 16
// baseline (speedup 1.0000x reference)
#include <cuda_runtime.h>
#include <cstdint>

#define SCORE_THRESH 0.05f
#define IOU_THRESH   0.5f
#define KTOP 1000
#define KPAD 1024
#define MAXDET 100
#define MAX_A (1 << 18)
#define NBLKF 32
#define NTHR 1024
#define ECAP 6144
#define DSMEM_FIN 49152
#define DSMEM_NMS 131072

// ---------------- device scratch ----------------
__device__ __align__(16) unsigned g_key[MAX_A];
__device__ __align__(16) unsigned long long g_ent[MAX_A];
__device__ unsigned long long  g_sorted[KPAD];
__device__ unsigned            g_hist0[2048];
__device__ unsigned            g_hist1[2048];
__device__ int                 g_entCount;
__device__ __align__(16) unsigned g_maskR[KPAD * 32];
__device__ float               g_rscore[KPAD];
__device__ unsigned            g_ridx[KPAD];
__device__ __align__(16) float g_rbox[KPAD * 4];
__device__ unsigned            g_barGen;
__device__ unsigned            g_barCnt;

__device__ __forceinline__ unsigned f2key(float f) {
    unsigned b = __float_as_uint(f);
    return (b & 0x80000000u) ? ~b : (b | 0x80000000u);
}
__device__ __forceinline__ float key2f(unsigned k) {
    unsigned b = (k & 0x80000000u) ? (k ^ 0x80000000u) : ~k;
    return __uint_as_float(b);
}

// flat grid barrier over NBLKF blocks
__device__ __forceinline__ void gsync() {
    __syncthreads();
    if (threadIdx.x == 0) {
        volatile unsigned* vg = &g_barGen;
        unsigned gen = *vg;
        __threadfence();
        if (atomicAdd(&g_barCnt, 1u) == NBLKF - 1) {
            atomicExch(&g_barCnt, 0u);
            __threadfence();
            atomicAdd(&g_barGen, 1u);
        } else {
            while (*vg == gen) __nanosleep(32);
        }
        __threadfence();
    }
    __syncthreads();
}

// ======= K1: per-anchor score + pass-0 histogram (proven 15.1us) ===========
__global__ void __launch_bounds__(256, 8)
k_score(const float* __restrict__ cls, int A, int C) {
    __shared__ unsigned sh[2048];
    for (int i = threadIdx.x; i < 2048; i += 256) sh[i] = 0;
    __syncthreads();
    int lane = threadIdx.x & 31;
    int gw = blockIdx.x * 8 + (threadIdx.x >> 5);
    int nw = gridDim.x * 8;
    if (C == 80) {
        const float4* p = (const float4*)cls;
        for (int a0 = gw * 8; a0 < A; a0 += nw * 8) {
            float m[8];
            #pragma unroll
            for (int r = 0; r < 8; ++r) m[r] = 0.0f;     // scores >= 0
            if (lane < 20) {
                #pragma unroll
                for (int r = 0; r < 8; ++r) {
                    int a = a0 + r;
                    if (a < A) {
                        float4 v = p[(size_t)a * 20 + lane];
                        m[r] = fmaxf(fmaxf(v.x, v.y), fmaxf(v.z, v.w));
                    }
                }
            }
            #pragma unroll
            for (int r = 0; r < 8; ++r) {
                unsigned u = __reduce_max_sync(0xFFFFFFFFu, __float_as_uint(m[r]));
                m[r] = __uint_as_float(u);
            }
            if (lane < 8) {
                float mv;
                switch (lane) {
                    case 0: mv = m[0]; break;
                    case 1: mv = m[1]; break;
                    case 2: mv = m[2]; break;
                    case 3: mv = m[3]; break;
                    case 4: mv = m[4]; break;
                    case 5: mv = m[5]; break;
                    case 6: mv = m[6]; break;
                    default: mv = m[7]; break;
                }
                int a = a0 + lane;
                bool valid = (a < A);
                unsigned k = f2key(mv > SCORE_THRESH ? mv : -1.0f);
                if (valid) g_key[a] = k;
                unsigned bin = valid ? (k >> 21) : (2048u + (unsigned)lane);
                unsigned mm = __match_any_sync(0xFFu, bin);
                if (valid && lane == (__ffs(mm) - 1))
                    atomicAdd(&sh[bin], (unsigned)__popc(mm));
            }
        }
    } else {
        for (int a = gw; a < A; a += nw) {
            float mm2 = -3.402823466e38f;
            const float* row = cls + (size_t)a * C;
            for (int c = lane; c < C; c += 32) mm2 = fmaxf(mm2, row[c]);
            #pragma unroll
            for (int o = 16; o; o >>= 1) mm2 = fmaxf(mm2, __shfl_down_sync(0xFFFFFFFFu, mm2, o));
            if (lane == 0) {
                unsigned k = f2key(mm2 > SCORE_THRESH ? mm2 : -1.0f);
                g_key[a] = k;
                atomicAdd(&sh[k >> 21], 1u);
            }
        }
    }
    __syncthreads();
    for (int i = threadIdx.x; i < 2048; i += 256) {
        unsigned v = sh[i];
        if (v) atomicAdd(&g_hist0[i], v);
    }
}

// block-local radix select, 3 barriers
__device__ void block_select(const unsigned* hist, int bins, unsigned krem,
                             unsigned* wsm, int* psel,
                             unsigned* pdig, unsigned* pkrem) {
    int t = threadIdx.x, lane = t & 31, w = t >> 5;
    int per = bins >> 10;
    unsigned c0 = hist[t * per];
    unsigned c1 = (per == 2) ? hist[t * per + 1] : 0u;
    unsigned tot = c0 + c1;
    if (t == 0) *psel = -1;
    unsigned s = tot;
    #pragma unroll
    for (int off = 1; off < 32; off <<= 1) {
        unsigned v = __shfl_down_sync(0xFFFFFFFFu, s, off);
        if (lane + off < 32) s += v;
    }
    if (lane == 0) wsm[w] = s;
    __syncthreads();
    if (t < 32) {
        unsigned wv = wsm[t];
        unsigned ws = wv;
        #pragma unroll
        for (int off = 1; off < 32; off <<= 1) {
            unsigned v = __shfl_down_sync(0xFFFFFFFFu, ws, off);
            if (t + off < 32) ws += v;
        }
        wsm[t] = ws - wv;
    }
    __syncthreads();
    unsigned suffExcl = wsm[w] + (s - tot);
    int best = -1; unsigned accAt = 0, cntAt = 0;
    unsigned acc = suffExcl;
    if (per == 2) {
        acc += c1;
        if (acc >= krem) { best = 2 * t + 1; accAt = acc; cntAt = c1; }
        else { acc += c0; if (acc >= krem) { best = 2 * t; accAt = acc; cntAt = c0; } }
    } else {
        acc += c0;
        if (acc >= krem) { best = t; accAt = acc; cntAt = c0; }
    }
    if (best >= 0) atomicMax(psel, best);
    __syncthreads();
    if (best >= 0 && best == *psel) {
        *pdig = (unsigned)best;
        *pkrem = krem - (accAt - cntAt);
    }
    __syncthreads();
}

// == K2 (32 blocks): select0+hist1 / select1+collect / rank / decode+mask ===
__global__ void __launch_bounds__(NTHR, 1)
k_fin(const float* __restrict__ reg, const float* __restrict__ anc,
      const int* __restrict__ pih, const int* __restrict__ piw, int A) {
    extern __shared__ unsigned char dsm[];
    __shared__ unsigned s_wsm[32];
    __shared__ int      s_sel;
    __shared__ unsigned s_dig;
    __shared__ unsigned s_krem;

    const int tid = threadIdx.x;
    const int bid = blockIdx.x;
    const int A4 = A >> 2;
    const int Atail = A4 << 2;

    unsigned pref0, krem1;
    {   // B0: select0 + pass-1 histogram
        block_select(g_hist0, 2048, KTOP, s_wsm, &s_sel, &s_dig, &s_krem);
        pref0 = s_dig; krem1 = s_krem;
        unsigned* sh = (unsigned*)dsm;
        for (int i = tid; i < 2048; i += NTHR) sh[i] = 0;
        __syncthreads();
        const uint4* kp = (const uint4*)g_key;
        for (int i = bid * NTHR + tid; i < A4; i += NBLKF * NTHR) {
            uint4 k = kp[i];
            if ((k.x >> 21) == pref0) atomicAdd(&sh[(k.x >> 10) & 0x7FFu], 1u);
            if ((k.y >> 21) == pref0) atomicAdd(&sh[(k.y >> 10) & 0x7FFu], 1u);
            if ((k.z >> 21) == pref0) atomicAdd(&sh[(k.z >> 10) & 0x7FFu], 1u);
            if ((k.w >> 21) == pref0) atomicAdd(&sh[(k.w >> 10) & 0x7FFu], 1u);
        }
        if (bid == 0) {
            for (int a = Atail + tid; a < A; a += NTHR) {
                unsigned k = g_key[a];
                if ((k >> 21) == pref0) atomicAdd(&sh[(k >> 10) & 0x7FFu], 1u);
            }
        }
        __syncthreads();
        for (int i = tid; i < 2048; i += NTHR) {
            unsigned v = sh[i];
            if (v) atomicAdd(&g_hist1[i], v);
        }
    }
    gsync();  // 1

    {   // B1: select1 -> 22-bit pivot; collect ALL entries key>>10 >= pivot22
        block_select(g_hist1, 2048, krem1, s_wsm, &s_sel, &s_dig, &s_krem);
        unsigned pivot22 = (pref0 << 11) | s_dig;
        const uint4* kp = (const uint4*)g_key;
        for (int i = bid * NTHR + tid; i < A4; i += NBLKF * NTHR) {
            uint4 kv = kp[i];
            unsigned base = (unsigned)(i << 2);
            #pragma unroll
            for (int c = 0; c < 4; ++c) {
                unsigned k = (c == 0) ? kv.x : (c == 1) ? kv.y : (c == 2) ? kv.z : kv.w;
                if ((k >> 10) >= pivot22) {
                    int p = atomicAdd(&g_entCount, 1);
                    g_ent[p] = ((unsigned long long)k << 32) |
                               (0xFFFFFFFFu - (base + (unsigned)c));
                }
            }
        }
        if (bid == 0) {
            for (int a = Atail + tid; a < A; a += NTHR) {
                unsigned k = g_key[a];
                if ((k >> 10) >= pivot22) {
                    int p = atomicAdd(&g_entCount, 1);
                    g_ent[p] = ((unsigned long long)k << 32) |
                               (0xFFFFFFFFu - (unsigned)a);
                }
            }
        }
    }
    gsync();  // 2

    {   // B2: full-rank each entry by u64 (warp per entry) -> g_sorted[rank]
        int E = g_entCount;
        if (bid == 0 && tid >= KTOP)      // padding slots
            g_sorted[tid] = (unsigned long long)(KPAD - tid);
        int wid = tid >> 5, lane = tid & 31;
        if (E <= ECAP) {
            unsigned long long* se = (unsigned long long*)dsm;   // 48KB
            for (int i = tid; i < E; i += NTHR) se[i] = g_ent[i];
            __syncthreads();
            for (int e = bid * 32 + wid; e < E; e += NBLKF * 32) {
                unsigned long long mine = se[e];
                int cnt = 0;
                for (int j = lane; j < E; j += 32) cnt += (se[j] > mine);
                cnt = __reduce_add_sync(0xFFFFFFFFu, cnt);
                if (lane == 0 && cnt < KTOP) g_sorted[cnt] = mine;
            }
        } else {
            // slow-but-correct fallback: rank from global memory
            for (int e = bid * 32 + wid; e < E; e += NBLKF * 32) {
                unsigned long long mine = g_ent[e];
                int cnt = 0;
                for (int j = lane; j < E; j += 32) cnt += (g_ent[j] > mine);
                cnt = __reduce_add_sync(0xFFFFFFFFu, cnt);
                if (lane == 0 && cnt < KTOP) g_sorted[cnt] = mine;
            }
        }
    }
    gsync();  // 3

    {   // B3: cleanup + decode in rank order (redundant) + triangle mask rows
        float4* sbox  = (float4*)dsm;                 // 16KB
        float*  sarea = (float*)(dsm + 16384);        // 4KB
        for (int i = bid * NTHR + tid; i < 2048; i += NBLKF * NTHR) g_hist0[i] = 0;
        for (int i = bid * NTHR + tid; i < 2048; i += NBLKF * NTHR) g_hist1[i] = 0;
        if (bid == 0 && tid == 0) g_entCount = 0;

        unsigned long long ck = g_sorted[tid];
        float score; float4 box; unsigned idx = 0;
        if (ck >= (1ULL << 32)) {
            unsigned key = (unsigned)(ck >> 32);
            idx = 0xFFFFFFFFu - (unsigned)(ck & 0xFFFFFFFFu);
            score = key2f(key);
            float4 a4 = ((const float4*)anc)[idx];
            float4 r4 = ((const float4*)reg)[idx];
            float aw = a4.z - a4.x, ah = a4.w - a4.y;
            float acx = a4.x + 0.5f * aw, acy = a4.y + 0.5f * ah;
            float pcx = acx + (r4.x * 0.1f) * aw;
            float pcy = acy + (r4.y * 0.1f) * ah;
            float pw = expf(r4.z * 0.2f) * aw;
            float ph = expf(r4.w * 0.2f) * ah;
            float W = (float)(*piw);
            float H = (float)(*pih);
            box.x = fminf(fmaxf(pcx - 0.5f * pw, 0.f), W);
            box.y = fminf(fmaxf(pcy - 0.5f * ph, 0.f), H);
            box.z = fminf(fmaxf(pcx + 0.5f * pw, 0.f), W);
            box.w = fminf(fmaxf(pcy + 0.5f * ph, 0.f), H);
        } else {
            score = -1.0f;
            box.x = box.y = box.z = box.w = 0.f;
        }
        sbox[tid] = box;
        sarea[tid] = fmaxf(box.z - box.x, 0.f) * fmaxf(box.w - box.y, 0.f);
        if (bid == 0) {
            g_rscore[tid] = score;
            g_ridx[tid] = idx;
            ((float4*)g_rbox)[tid] = box;
        }
        __syncthreads();
        float4 cb = sbox[tid];
        float  ca = sarea[tid];
        for (int r = bid; r < KPAD; r += NBLKF) {
            bool sup = false;
            if (tid > r) {
                float4 rb = sbox[r];
                float  ra = sarea[r];
                float xx1 = fmaxf(rb.x, cb.x);
                float yy1 = fmaxf(rb.y, cb.y);
                float xx2 = fminf(rb.z, cb.z);
                float yy2 = fminf(rb.w, cb.w);
                float inter = fmaxf(xx2 - xx1, 0.f) * fmaxf(yy2 - yy1, 0.f);
                float denom = ra + ca - inter + 1e-8f;
                sup = inter > IOU_THRESH * denom;
            }
            unsigned ball = __ballot_sync(0xFFFFFFFFu, sup);
            if ((tid & 31) == 0) g_maskR[r * 32 + (tid >> 5)] = ball;
        }
    }
}

// ======= K3 (1 block): NMS scan + final outputs ============================
__global__ void __launch_bounds__(NTHR, 1)
k_nms(const float* __restrict__ cls, float* __restrict__ out, int C) {
    extern __shared__ unsigned char dsm[];
    __shared__ int s_dc;
    __shared__ int s_det[128];
    int tid = threadIdx.x;
    unsigned* smask = (unsigned*)dsm;
    {
        const uint4* gm = (const uint4*)g_maskR;
        uint4* sm4 = (uint4*)smask;
        for (int i = tid; i < KPAD * 8; i += NTHR) sm4[i] = gm[i];
    }
    int myvalid = (g_rscore[tid] > SCORE_THRESH) ? 1 : 0;
    int nvalid = __syncthreads_count(myvalid);   // valid = rank prefix
    if (tid < 32) {
        int base = tid * 32;
        unsigned alive;
        if (nvalid >= base + 32)      alive = 0xFFFFFFFFu;
        else if (nvalid <= base)      alive = 0u;
        else                          alive = (1u << (nvalid - base)) - 1u;
        unsigned rem = 0;
        int dc = 0;
        while (dc < MAXDET) {
            unsigned av = alive & ~rem;
            unsigned ball = __ballot_sync(0xFFFFFFFFu, av != 0u);
            if (!ball) break;
            int grp = __ffs(ball) - 1;
            unsigned gav = __shfl_sync(0xFFFFFFFFu, av, grp);
            int b = __ffs(gav) - 1;
            int rank = (grp << 5) + b;
            if (tid == 0) s_det[dc] = rank;
            dc++;
            if (tid == grp) alive &= ~(1u << b);
            rem |= smask[rank * 32 + tid];
        }
        if (tid == 0) s_dc = dc;
    }
    __syncthreads();
    int dc = s_dc;
    int lane = tid & 31;
    int w = tid >> 5;
    for (int d = w; d < MAXDET; d += 32) {
        if (d < dc) {
            int rank = s_det[d];
            unsigned idx = g_ridx[rank];
            const float* row = cls + (size_t)idx * C;
            float bv = -3.402823466e38f; int bi = 0;
            for (int c = lane; c < C; c += 32) {
                float v = row[c];
                if (v > bv) { bv = v; bi = c; }
            }
            #pragma unroll
            for (int o = 16; o; o >>= 1) {
                float ov = __shfl_down_sync(0xFFFFFFFFu, bv, o);
                int   oi = __shfl_down_sync(0xFFFFFFFFu, bi, o);
                if (ov > bv || (ov == bv && oi < bi)) { bv = ov; bi = oi; }
            }
            if (lane == 0) {
                out[d] = g_rscore[rank];
                out[100 + d] = (float)bi;
                out[200 + 4 * d + 0] = g_rbox[4 * rank + 0];
                out[200 + 4 * d + 1] = g_rbox[4 * rank + 1];
                out[200 + 4 * d + 2] = g_rbox[4 * rank + 2];
                out[200 + 4 * d + 3] = g_rbox[4 * rank + 3];
            }
        } else if (lane == 0) {
            out[d] = 0.0f;
            out[100 + d] = -1.0f;
            out[200 + 4 * d + 0] = 0.0f; out[200 + 4 * d + 1] = 0.0f;
            out[200 + 4 * d + 2] = 0.0f; out[200 + 4 * d + 3] = 0.0f;
        }
    }
}

// ---------------- host launcher ----------------
extern "C" void kernel_launch(void* const* d_in, const int* in_sizes, int n_in,
                              void* d_out, int out_size) {
    const float* cls = (const float*)d_in[0];
    const float* reg = (const float*)d_in[1];
    const float* anc = (const float*)d_in[2];
    const int* ih = (const int*)d_in[3];
    const int* iw = (const int*)d_in[4];

    int A = in_sizes[1] / 4;
    int C = (A > 0) ? (in_sizes[0] / A) : 80;
    float* out = (float*)d_out;
    (void)out_size; (void)n_in;

    cudaFuncSetAttribute(k_fin, cudaFuncAttributeMaxDynamicSharedMemorySize, DSMEM_FIN);
    cudaFuncSetAttribute(k_nms, cudaFuncAttributeMaxDynamicSharedMemorySize, DSMEM_NMS);

    k_score<<<1184, 256>>>(cls, A, C);
    k_fin<<<NBLKF, NTHR, DSMEM_FIN>>>(reg, anc, ih, iw, A);
    k_nms<<<1, NTHR, DSMEM_NMS>>>(cls, out, C);
}

// round 17
// speedup vs baseline: 1.0823x; 1.0823x over previous
#include <cuda_runtime.h>
#include <cstdint>

#define SCORE_THRESH 0.05f
#define IOU_THRESH   0.5f
#define KTOP 1000
#define KPAD 1024
#define MAXDET 100
#define MAX_A (1 << 18)
#define NBLK 148
#define NTHR 1024
#define ECAP 6144
#define DSMEM_FIN 49152
#define DSMEM_NMS 131072

// ---------------- device scratch ----------------
__device__ __align__(16) unsigned g_key[MAX_A];
__device__ __align__(16) unsigned long long g_ent[MAX_A];
__device__ unsigned long long  g_sorted[KPAD];
__device__ unsigned            g_hist0[2048];
__device__ unsigned            g_hist1[2048];
__device__ int                 g_entCount;
__device__ __align__(16) unsigned g_maskR[KPAD * 32];
__device__ float               g_rscore[KPAD];
__device__ unsigned            g_ridx[KPAD];
__device__ __align__(16) float g_rbox[KPAD * 4];
__device__ unsigned            g_barGen;
__device__ unsigned            g_barCnt;

__device__ __forceinline__ unsigned f2key(float f) {
    unsigned b = __float_as_uint(f);
    return (b & 0x80000000u) ? ~b : (b | 0x80000000u);
}
__device__ __forceinline__ float key2f(unsigned k) {
    unsigned b = (k & 0x80000000u) ? (k ^ 0x80000000u) : ~k;
    return __uint_as_float(b);
}

// flat grid barrier (R10/R15-proven)
__device__ __forceinline__ void gsync() {
    __syncthreads();
    if (threadIdx.x == 0) {
        volatile unsigned* vg = &g_barGen;
        unsigned gen = *vg;
        __threadfence();
        if (atomicAdd(&g_barCnt, 1u) == NBLK - 1) {
            atomicExch(&g_barCnt, 0u);
            __threadfence();
            atomicAdd(&g_barGen, 1u);
        } else {
            while (*vg == gen) __nanosleep(32);
        }
        __threadfence();
    }
    __syncthreads();
}

// ======= K1: per-anchor score + pass-0 histogram (MLP-8 load batch) ========
__global__ void __launch_bounds__(256, 6)
k_score(const float* __restrict__ cls, int A, int C) {
    __shared__ unsigned sh[2048];
    for (int i = threadIdx.x; i < 2048; i += 256) sh[i] = 0;
    __syncthreads();
    int lane = threadIdx.x & 31;
    int gw = blockIdx.x * 8 + (threadIdx.x >> 5);
    int nw = gridDim.x * 8;
    if (C == 80) {
        const float4* p = (const float4*)cls;
        for (int a0 = gw * 8; a0 < A; a0 += nw * 8) {
            // batch all 8 loads into registers first -> 8 LDG.128 in flight
            float4 v[8];
            #pragma unroll
            for (int r = 0; r < 8; ++r) v[r] = make_float4(0.f, 0.f, 0.f, 0.f);
            if (lane < 20) {
                if (a0 + 7 < A) {
                    #pragma unroll
                    for (int r = 0; r < 8; ++r)
                        v[r] = p[(size_t)(a0 + r) * 20 + lane];
                } else {
                    #pragma unroll
                    for (int r = 0; r < 8; ++r)
                        if (a0 + r < A) v[r] = p[(size_t)(a0 + r) * 20 + lane];
                }
            }
            float m[8];
            #pragma unroll
            for (int r = 0; r < 8; ++r)
                m[r] = fmaxf(fmaxf(v[r].x, v[r].y), fmaxf(v[r].z, v[r].w));
            #pragma unroll
            for (int r = 0; r < 8; ++r) {
                unsigned u = __reduce_max_sync(0xFFFFFFFFu, __float_as_uint(m[r]));
                m[r] = __uint_as_float(u);
            }
            if (lane < 8) {
                float mv;
                switch (lane) {
                    case 0: mv = m[0]; break;
                    case 1: mv = m[1]; break;
                    case 2: mv = m[2]; break;
                    case 3: mv = m[3]; break;
                    case 4: mv = m[4]; break;
                    case 5: mv = m[5]; break;
                    case 6: mv = m[6]; break;
                    default: mv = m[7]; break;
                }
                int a = a0 + lane;
                bool valid = (a < A);
                unsigned k = f2key(mv > SCORE_THRESH ? mv : -1.0f);
                if (valid) g_key[a] = k;
                unsigned bin = valid ? (k >> 21) : (2048u + (unsigned)lane);
                unsigned mm = __match_any_sync(0xFFu, bin);
                if (valid && lane == (__ffs(mm) - 1))
                    atomicAdd(&sh[bin], (unsigned)__popc(mm));
            }
        }
    } else {
        for (int a = gw; a < A; a += nw) {
            float mm2 = -3.402823466e38f;
            const float* row = cls + (size_t)a * C;
            for (int c = lane; c < C; c += 32) mm2 = fmaxf(mm2, row[c]);
            #pragma unroll
            for (int o = 16; o; o >>= 1) mm2 = fmaxf(mm2, __shfl_down_sync(0xFFFFFFFFu, mm2, o));
            if (lane == 0) {
                unsigned k = f2key(mm2 > SCORE_THRESH ? mm2 : -1.0f);
                g_key[a] = k;
                atomicAdd(&sh[k >> 21], 1u);
            }
        }
    }
    __syncthreads();
    for (int i = threadIdx.x; i < 2048; i += 256) {
        unsigned v = sh[i];
        if (v) atomicAdd(&g_hist0[i], v);
    }
}

// block-local radix select, 3 barriers
__device__ void block_select(const unsigned* hist, int bins, unsigned krem,
                             unsigned* wsm, int* psel,
                             unsigned* pdig, unsigned* pkrem) {
    int t = threadIdx.x, lane = t & 31, w = t >> 5;
    int per = bins >> 10;
    unsigned c0 = hist[t * per];
    unsigned c1 = (per == 2) ? hist[t * per + 1] : 0u;
    unsigned tot = c0 + c1;
    if (t == 0) *psel = -1;
    unsigned s = tot;
    #pragma unroll
    for (int off = 1; off < 32; off <<= 1) {
        unsigned v = __shfl_down_sync(0xFFFFFFFFu, s, off);
        if (lane + off < 32) s += v;
    }
    if (lane == 0) wsm[w] = s;
    __syncthreads();
    if (t < 32) {
        unsigned wv = wsm[t];
        unsigned ws = wv;
        #pragma unroll
        for (int off = 1; off < 32; off <<= 1) {
            unsigned v = __shfl_down_sync(0xFFFFFFFFu, ws, off);
            if (t + off < 32) ws += v;
        }
        wsm[t] = ws - wv;
    }
    __syncthreads();
    unsigned suffExcl = wsm[w] + (s - tot);
    int best = -1; unsigned accAt = 0, cntAt = 0;
    unsigned acc = suffExcl;
    if (per == 2) {
        acc += c1;
        if (acc >= krem) { best = 2 * t + 1; accAt = acc; cntAt = c1; }
        else { acc += c0; if (acc >= krem) { best = 2 * t; accAt = acc; cntAt = c0; } }
    } else {
        acc += c0;
        if (acc >= krem) { best = t; accAt = acc; cntAt = c0; }
    }
    if (best >= 0) atomicMax(psel, best);
    __syncthreads();
    if (best >= 0 && best == *psel) {
        *pdig = (unsigned)best;
        *pkrem = krem - (accAt - cntAt);
    }
    __syncthreads();
}

// == K2: select0+hist1 / select1+collect / full-rank / decode+mask ==========
__global__ void __launch_bounds__(NTHR, 1)
k_fin(const float* __restrict__ reg, const float* __restrict__ anc,
      const int* __restrict__ pih, const int* __restrict__ piw, int A) {
    extern __shared__ unsigned char dsm[];
    __shared__ unsigned s_wsm[32];
    __shared__ int      s_sel;
    __shared__ unsigned s_dig;
    __shared__ unsigned s_krem;

    const int tid = threadIdx.x;
    const int bid = blockIdx.x;
    const int A4 = A >> 2;
    const int Atail = A4 << 2;

    unsigned pref0, krem1;
    {   // B0: select0 + pass-1 histogram
        block_select(g_hist0, 2048, KTOP, s_wsm, &s_sel, &s_dig, &s_krem);
        pref0 = s_dig; krem1 = s_krem;
        unsigned* sh = (unsigned*)dsm;
        for (int i = tid; i < 2048; i += NTHR) sh[i] = 0;
        __syncthreads();
        const uint4* kp = (const uint4*)g_key;
        for (int i = bid * NTHR + tid; i < A4; i += NBLK * NTHR) {
            uint4 k = kp[i];
            if ((k.x >> 21) == pref0) atomicAdd(&sh[(k.x >> 10) & 0x7FFu], 1u);
            if ((k.y >> 21) == pref0) atomicAdd(&sh[(k.y >> 10) & 0x7FFu], 1u);
            if ((k.z >> 21) == pref0) atomicAdd(&sh[(k.z >> 10) & 0x7FFu], 1u);
            if ((k.w >> 21) == pref0) atomicAdd(&sh[(k.w >> 10) & 0x7FFu], 1u);
        }
        if (bid == 0) {
            for (int a = Atail + tid; a < A; a += NTHR) {
                unsigned k = g_key[a];
                if ((k >> 21) == pref0) atomicAdd(&sh[(k >> 10) & 0x7FFu], 1u);
            }
        }
        __syncthreads();
        for (int i = tid; i < 2048; i += NTHR) {
            unsigned v = sh[i];
            if (v) atomicAdd(&g_hist1[i], v);
        }
    }
    gsync();  // 1

    {   // B1: select1 -> 22-bit pivot; collect ALL entries key>>10 >= pivot22
        block_select(g_hist1, 2048, krem1, s_wsm, &s_sel, &s_dig, &s_krem);
        unsigned pivot22 = (pref0 << 11) | s_dig;
        const uint4* kp = (const uint4*)g_key;
        for (int i = bid * NTHR + tid; i < A4; i += NBLK * NTHR) {
            uint4 kv = kp[i];
            unsigned base = (unsigned)(i << 2);
            #pragma unroll
            for (int c = 0; c < 4; ++c) {
                unsigned k = (c == 0) ? kv.x : (c == 1) ? kv.y : (c == 2) ? kv.z : kv.w;
                if ((k >> 10) >= pivot22) {
                    int p = atomicAdd(&g_entCount, 1);
                    g_ent[p] = ((unsigned long long)k << 32) |
                               (0xFFFFFFFFu - (base + (unsigned)c));
                }
            }
        }
        if (bid == 0) {
            for (int a = Atail + tid; a < A; a += NTHR) {
                unsigned k = g_key[a];
                if ((k >> 10) >= pivot22) {
                    int p = atomicAdd(&g_entCount, 1);
                    g_ent[p] = ((unsigned long long)k << 32) |
                               (0xFFFFFFFFu - (unsigned)a);
                }
            }
        }
    }
    gsync();  // 2

    {   // B2: full-rank each entry by u64 (warp per entry) -> g_sorted[rank]
        int E = g_entCount;
        if (bid == 0 && tid >= KTOP)      // padding slots
            g_sorted[tid] = (unsigned long long)(KPAD - tid);
        int wid = tid >> 5, lane = tid & 31;
        if (E <= ECAP) {
            unsigned long long* se = (unsigned long long*)dsm;   // 48KB
            for (int i = tid; i < E; i += NTHR) se[i] = g_ent[i];
            __syncthreads();
            for (int e = bid * 32 + wid; e < E; e += NBLK * 32) {
                unsigned long long mine = se[e];
                int cnt = 0;
                for (int j = lane; j < E; j += 32) cnt += (se[j] > mine);
                cnt = __reduce_add_sync(0xFFFFFFFFu, cnt);
                if (lane == 0 && cnt < KTOP) g_sorted[cnt] = mine;
            }
        } else {
            // slow-but-correct fallback: rank from global memory
            for (int e = bid * 32 + wid; e < E; e += NBLK * 32) {
                unsigned long long mine = g_ent[e];
                int cnt = 0;
                for (int j = lane; j < E; j += 32) cnt += (g_ent[j] > mine);
                cnt = __reduce_add_sync(0xFFFFFFFFu, cnt);
                if (lane == 0 && cnt < KTOP) g_sorted[cnt] = mine;
            }
        }
    }
    gsync();  // 3

    {   // B3: cleanup + decode in rank order (redundant) + triangle mask rows
        float4* sbox  = (float4*)dsm;                 // 16KB
        float*  sarea = (float*)(dsm + 16384);        // 4KB
        for (int i = bid * NTHR + tid; i < 2048; i += NBLK * NTHR) g_hist0[i] = 0;
        for (int i = bid * NTHR + tid; i < 2048; i += NBLK * NTHR) g_hist1[i] = 0;
        if (bid == 0 && tid == 0) g_entCount = 0;

        unsigned long long ck = g_sorted[tid];
        float score; float4 box; unsigned idx = 0;
        if (ck >= (1ULL << 32)) {
            unsigned key = (unsigned)(ck >> 32);
            idx = 0xFFFFFFFFu - (unsigned)(ck & 0xFFFFFFFFu);
            score = key2f(key);
            float4 a4 = ((const float4*)anc)[idx];
            float4 r4 = ((const float4*)reg)[idx];
            float aw = a4.z - a4.x, ah = a4.w - a4.y;
            float acx = a4.x + 0.5f * aw, acy = a4.y + 0.5f * ah;
            float pcx = acx + (r4.x * 0.1f) * aw;
            float pcy = acy + (r4.y * 0.1f) * ah;
            float pw = expf(r4.z * 0.2f) * aw;
            float ph = expf(r4.w * 0.2f) * ah;
            float W = (float)(*piw);
            float H = (float)(*pih);
            box.x = fminf(fmaxf(pcx - 0.5f * pw, 0.f), W);
            box.y = fminf(fmaxf(pcy - 0.5f * ph, 0.f), H);
            box.z = fminf(fmaxf(pcx + 0.5f * pw, 0.f), W);
            box.w = fminf(fmaxf(pcy + 0.5f * ph, 0.f), H);
        } else {
            score = -1.0f;
            box.x = box.y = box.z = box.w = 0.f;
        }
        sbox[tid] = box;
        sarea[tid] = fmaxf(box.z - box.x, 0.f) * fmaxf(box.w - box.y, 0.f);
        if (bid == 0) {
            g_rscore[tid] = score;
            g_ridx[tid] = idx;
            ((float4*)g_rbox)[tid] = box;
        }
        __syncthreads();
        float4 cb = sbox[tid];
        float  ca = sarea[tid];
        for (int r = bid; r < KPAD; r += NBLK) {
            bool sup = false;
            if (tid > r) {
                float4 rb = sbox[r];
                float  ra = sarea[r];
                float xx1 = fmaxf(rb.x, cb.x);
                float yy1 = fmaxf(rb.y, cb.y);
                float xx2 = fminf(rb.z, cb.z);
                float yy2 = fminf(rb.w, cb.w);
                float inter = fmaxf(xx2 - xx1, 0.f) * fmaxf(yy2 - yy1, 0.f);
                float denom = ra + ca - inter + 1e-8f;
                sup = inter > IOU_THRESH * denom;
            }
            unsigned ball = __ballot_sync(0xFFFFFFFFu, sup);
            if ((tid & 31) == 0) g_maskR[r * 32 + (tid >> 5)] = ball;
        }
    }
}

// ======= K3 (1 block): NMS scan + final outputs ============================
__global__ void __launch_bounds__(NTHR, 1)
k_nms(const float* __restrict__ cls, float* __restrict__ out, int C) {
    extern __shared__ unsigned char dsm[];
    __shared__ int s_dc;
    __shared__ int s_det[128];
    int tid = threadIdx.x;
    unsigned* smask = (unsigned*)dsm;
    {
        const uint4* gm = (const uint4*)g_maskR;
        uint4* sm4 = (uint4*)smask;
        for (int i = tid; i < KPAD * 8; i += NTHR) sm4[i] = gm[i];
    }
    int myvalid = (g_rscore[tid] > SCORE_THRESH) ? 1 : 0;
    int nvalid = __syncthreads_count(myvalid);   // valid = rank prefix
    if (tid < 32) {
        int base = tid * 32;
        unsigned alive;
        if (nvalid >= base + 32)      alive = 0xFFFFFFFFu;
        else if (nvalid <= base)      alive = 0u;
        else                          alive = (1u << (nvalid - base)) - 1u;
        unsigned rem = 0;
        int dc = 0;
        while (dc < MAXDET) {
            unsigned av = alive & ~rem;
            unsigned ball = __ballot_sync(0xFFFFFFFFu, av != 0u);
            if (!ball) break;
            int grp = __ffs(ball) - 1;
            unsigned gav = __shfl_sync(0xFFFFFFFFu, av, grp);
            int b = __ffs(gav) - 1;
            int rank = (grp << 5) + b;
            if (tid == 0) s_det[dc] = rank;
            dc++;
            if (tid == grp) alive &= ~(1u << b);
            rem |= smask[rank * 32 + tid];
        }
        if (tid == 0) s_dc = dc;
    }
    __syncthreads();
    int dc = s_dc;
    int lane = tid & 31;
    int w = tid >> 5;
    for (int d = w; d < MAXDET; d += 32) {
        if (d < dc) {
            int rank = s_det[d];
            unsigned idx = g_ridx[rank];
            const float* row = cls + (size_t)idx * C;
            float bv = -3.402823466e38f; int bi = 0;
            for (int c = lane; c < C; c += 32) {
                float v = row[c];
                if (v > bv) { bv = v; bi = c; }
            }
            #pragma unroll
            for (int o = 16; o; o >>= 1) {
                float ov = __shfl_down_sync(0xFFFFFFFFu, bv, o);
                int   oi = __shfl_down_sync(0xFFFFFFFFu, bi, o);
                if (ov > bv || (ov == bv && oi < bi)) { bv = ov; bi = oi; }
            }
            if (lane == 0) {
                out[d] = g_rscore[rank];
                out[100 + d] = (float)bi;
                out[200 + 4 * d + 0] = g_rbox[4 * rank + 0];
                out[200 + 4 * d + 1] = g_rbox[4 * rank + 1];
                out[200 + 4 * d + 2] = g_rbox[4 * rank + 2];
                out[200 + 4 * d + 3] = g_rbox[4 * rank + 3];
            }
        } else if (lane == 0) {
            out[d] = 0.0f;
            out[100 + d] = -1.0f;
            out[200 + 4 * d + 0] = 0.0f; out[200 + 4 * d + 1] = 0.0f;
            out[200 + 4 * d + 2] = 0.0f; out[200 + 4 * d + 3] = 0.0f;
        }
    }
}

// ---------------- host launcher ----------------
extern "C" void kernel_launch(void* const* d_in, const int* in_sizes, int n_in,
                              void* d_out, int out_size) {
    const float* cls = (const float*)d_in[0];
    const float* reg = (const float*)d_in[1];
    const float* anc = (const float*)d_in[2];
    const int* ih = (const int*)d_in[3];
    const int* iw = (const int*)d_in[4];

    int A = in_sizes[1] / 4;
    int C = (A > 0) ? (in_sizes[0] / A) : 80;
    float* out = (float*)d_out;
    (void)out_size; (void)n_in;

    cudaFuncSetAttribute(k_fin, cudaFuncAttributeMaxDynamicSharedMemorySize, DSMEM_FIN);
    cudaFuncSetAttribute(k_nms, cudaFuncAttributeMaxDynamicSharedMemorySize, DSMEM_NMS);

    k_score<<<1184, 256>>>(cls, A, C);
    k_fin<<<NBLK, NTHR, DSMEM_FIN>>>(reg, anc, ih, iw, A);
    k_nms<<<1, NTHR, DSMEM_NMS>>>(cls, out, C);
}